// round 1
// baseline (speedup 1.0000x reference)
#include <cuda_runtime.h>

// BP-MLL loss, factorized per row:
//   s_pos = sum_{t==1} exp(-x), s_neg = sum_{t==0} exp(x)
//   loss  = sum_rows s_pos*s_neg / (n_pos*n_neg)
//
// Streaming HBM-bound reduction: 655 MB read once.

#define BB 8192
#define LL 10000
#define LL4 (LL / 4)          // 2500 vec4 chunks per row
#define NTHR 256

// Scratch for per-row partial results (no device allocation allowed).
__device__ float g_row_partial[BB];

__global__ __launch_bounds__(NTHR)
void bpmll_row_kernel(const float4* __restrict__ x4,
                      const int4*   __restrict__ t4)
{
    const int row = blockIdx.x;
    const float4* xr = x4 + (size_t)row * LL4;
    const int4*   tr = t4 + (size_t)row * LL4;

    float sp = 0.0f;   // sum exp(-x) over positives
    float sn = 0.0f;   // sum exp(+x) over negatives
    int   np = 0;      // positive count

    for (int i = threadIdx.x; i < LL4; i += NTHR) {
        float4 xv = xr[i];
        int4   tv = tr[i];

        {
            float e = __expf(tv.x ? -xv.x : xv.x);
            if (tv.x) { sp += e; np++; } else { sn += e; }
        }
        {
            float e = __expf(tv.y ? -xv.y : xv.y);
            if (tv.y) { sp += e; np++; } else { sn += e; }
        }
        {
            float e = __expf(tv.z ? -xv.z : xv.z);
            if (tv.z) { sp += e; np++; } else { sn += e; }
        }
        {
            float e = __expf(tv.w ? -xv.w : xv.w);
            if (tv.w) { sp += e; np++; } else { sn += e; }
        }
    }

    // Warp reduction
    #pragma unroll
    for (int off = 16; off > 0; off >>= 1) {
        sp += __shfl_down_sync(0xFFFFFFFFu, sp, off);
        sn += __shfl_down_sync(0xFFFFFFFFu, sn, off);
        np += __shfl_down_sync(0xFFFFFFFFu, np, off);
    }

    __shared__ float s_sp[NTHR / 32];
    __shared__ float s_sn[NTHR / 32];
    __shared__ int   s_np[NTHR / 32];

    const int lane = threadIdx.x & 31;
    const int wid  = threadIdx.x >> 5;
    if (lane == 0) { s_sp[wid] = sp; s_sn[wid] = sn; s_np[wid] = np; }
    __syncthreads();

    if (wid == 0) {
        sp = (lane < NTHR / 32) ? s_sp[lane] : 0.0f;
        sn = (lane < NTHR / 32) ? s_sn[lane] : 0.0f;
        np = (lane < NTHR / 32) ? s_np[lane] : 0;
        #pragma unroll
        for (int off = (NTHR / 64); off > 0; off >>= 1) {
            sp += __shfl_down_sync(0xFFFFFFFFu, sp, off);
            sn += __shfl_down_sync(0xFFFFFFFFu, sn, off);
            np += __shfl_down_sync(0xFFFFFFFFu, np, off);
        }
        if (lane == 0) {
            const float k = (float)np * (float)(LL - np);
            g_row_partial[row] = sp * sn / k;
        }
    }
}

// Deterministic final reduction of 8192 row partials -> scalar.
__global__ __launch_bounds__(NTHR)
void bpmll_final_kernel(float* __restrict__ out)
{
    float s = 0.0f;
    for (int i = threadIdx.x; i < BB; i += NTHR)
        s += g_row_partial[i];

    #pragma unroll
    for (int off = 16; off > 0; off >>= 1)
        s += __shfl_down_sync(0xFFFFFFFFu, s, off);

    __shared__ float smem[NTHR / 32];
    const int lane = threadIdx.x & 31;
    const int wid  = threadIdx.x >> 5;
    if (lane == 0) smem[wid] = s;
    __syncthreads();

    if (wid == 0) {
        s = (lane < NTHR / 32) ? smem[lane] : 0.0f;
        #pragma unroll
        for (int off = (NTHR / 64); off > 0; off >>= 1)
            s += __shfl_down_sync(0xFFFFFFFFu, s, off);
        if (lane == 0) out[0] = s;
    }
}

extern "C" void kernel_launch(void* const* d_in, const int* in_sizes, int n_in,
                              void* d_out, int out_size)
{
    const float4* x4 = (const float4*)d_in[0];
    const int4*   t4 = (const int4*)d_in[1];
    float* out = (float*)d_out;

    bpmll_row_kernel<<<BB, NTHR>>>(x4, t4);
    bpmll_final_kernel<<<1, NTHR>>>(out);
}